// round 6
// baseline (speedup 1.0000x reference)
#include <cuda_runtime.h>
#include <cuda_bf16.h>

// BrockHommes exact sequential scan, lag-4 dependence => 4-way parallel.
// One warp; lanes 0..3 of each quad compute one timestep of the group of 4
// (replicated across 8 quads => warp stays converged, no WARPSYNC). Window
// exchanged with two width-4 shuffles per group. Softmax shifted by branch 0
// (q0==1), raw EX2/RCP MUFU ops. 1/R folded into the y coefficients so the
// epilogue is fma(S1', rcp(S0), es). MUFU issue order d3,d2,d1 with both
// reduction trees ending on the last-ready q1.

__device__ __forceinline__ float ex2a(float x) {
    float r; asm("ex2.approx.ftz.f32 %0, %1;" : "=f"(r) : "f"(x)); return r;
}
__device__ __forceinline__ float rcpa(float x) {
    float r; asm("rcp.approx.ftz.f32 %0, %1;" : "=f"(r) : "f"(x)); return r;
}

__global__ void __launch_bounds__(32, 1) bh_scan_kernel(
    const float* __restrict__ params,
    const float* __restrict__ eps,
    float* __restrict__ out,
    int n)
{
    const int lane = (int)threadIdx.x;
    const int lq   = lane & 3;

    // --- derived parameters (uniform) ---
    const float beta  = expf(params[0]);
    const float sigma = expf(params[9]);          // params[-2]
    const float R     = 1.0f + expf(params[10]);  // params[-1]
    const float negR  = -R;
    const float Rinv  = 1.0f / R;
    const float sigR  = sigma * Rinv;
    const float beta2 = beta * 1.44269504088896340736f;  // beta * log2(e)

    const float g0 = params[1], g1 = params[2], g2 = params[3], g3 = params[4];
    const float b0 = params[5], b1 = params[6], b2 = params[7], b3 = params[8];

    // y' coefficients with 1/R folded in: y'_i = g'_i*p4 + b'_i, S1' = S1/R
    const float g0p = g0 * Rinv, g1p = g1 * Rinv, g2p = g2 * Rinv, g3p = g3 * Rinv;
    const float b0p = b0 * Rinv, b1p = b1 * Rinv, b2p = b2 * Rinv, b3p = b3 * Rinv;

    // exponent diffs vs branch 0 (beta*log2e folded)
    const float bdg1 = beta2 * (g1 - g0), bdb1 = beta2 * (b1 - b0);
    const float bdg2 = beta2 * (g2 - g0), bdb2 = beta2 * (b2 - b0);
    const float bdg3 = beta2 * (g3 - g0), bdb3 = beta2 * (b3 - b0);

    const int  srcA = (lq + 3) & 3;   // p5 source within quad
    const int  srcB = (lq + 2) & 3;   // p6 source within quad
    const bool is3  = (lq == 3);
    const bool hi2  = (lq >= 2);
    const bool q0w  = (lane < 4);     // only quad 0 commits stores

    // window for t = 4*grp + lq: p4=x_{t-4}, p5=x_{t-5}, p6=x_{t-6}
    float p4 = 0.0f, p5 = 0.0f, p6 = 0.0f;

    const int ngroups = n >> 2;
    const int nmain   = (ngroups > 3) ? (ngroups - 3) : 0;
    int t = lq;
    // depth-3 epsilon prefetch (L2 hit ~234 cyc > 2 groups of chain)
    float eA = (t     < n) ? eps[t]     : 0.0f;
    float eB = (t + 4 < n) ? eps[t + 4] : 0.0f;
    float eC = (t + 8 < n) ? eps[t + 8] : 0.0f;

    // main loop: t+12 <= 4*(nmain-1)+3+12 = 4*ngroups - 1 < n  => in bounds
    #pragma unroll 8
    for (int grp = 0; grp < nmain; ++grp, t += 4) {
        const float es = eA * sigR;            // off-chain
        eA = eB; eB = eC;
        eC = eps[t + 12];                      // unconditional prefetch

        // y' from own p4 (known since last group end) — shuffle shadow work
        const float y0p = fmaf(g0p, p4, b0p);
        const float y1p = fmaf(g1p, p4, b1p);
        const float y2p = fmaf(g2p, p4, b2p);
        const float y3p = fmaf(g3p, p4, b3p);

        // --- critical chain ---
        const float am = fmaf(negR, p5, p4);   // xm4 - R*xm5
        const float c3 = fmaf(bdg3, p6, bdb3);
        const float c2 = fmaf(bdg2, p6, bdb2);
        const float c1 = fmaf(bdg1, p6, bdb1);
        const float q3 = ex2a(am * c3);        // issued first -> ready first
        const float q2 = ex2a(am * c2);
        const float q1 = ex2a(am * c1);        // last-ready

        const float S0 = ((q3 + q2) + 1.0f) + q1;  // q1 at depth 1
        float s = fmaf(q3, y3p, y0p);
        s = fmaf(q2, y2p, s);
        const float S1p = fmaf(q1, y1p, s);        // ends on q1

        const float r0 = rcpa(S0);
        const float x  = fmaf(S1p, r0, es);

        if (q0w) out[t] = x;                   // predicated STG

        // --- window update: 2 width-4 shuffles, converged warp ---
        const float u = is3 ? p4 : x;
        const float v = hi2 ? p4 : x;
        p5 = __shfl_sync(0xFFFFFFFFu, u, srcA, 4);
        p6 = __shfl_sync(0xFFFFFFFFu, v, srcB, 4);
        p4 = x;
    }

    // last few full groups: guarded prefetch
    for (int grp = nmain; grp < ngroups; ++grp, t += 4) {
        const float es = eA * sigR;
        eA = eB; eB = eC;
        eC = (t + 12 < n) ? eps[t + 12] : 0.0f;

        const float y0p = fmaf(g0p, p4, b0p);
        const float y1p = fmaf(g1p, p4, b1p);
        const float y2p = fmaf(g2p, p4, b2p);
        const float y3p = fmaf(g3p, p4, b3p);

        const float am = fmaf(negR, p5, p4);
        const float c3 = fmaf(bdg3, p6, bdb3);
        const float c2 = fmaf(bdg2, p6, bdb2);
        const float c1 = fmaf(bdg1, p6, bdb1);
        const float q3 = ex2a(am * c3);
        const float q2 = ex2a(am * c2);
        const float q1 = ex2a(am * c1);

        const float S0 = ((q3 + q2) + 1.0f) + q1;
        float s = fmaf(q3, y3p, y0p);
        s = fmaf(q2, y2p, s);
        const float S1p = fmaf(q1, y1p, s);

        const float x = fmaf(S1p, rcpa(S0), es);

        if (q0w) out[t] = x;

        const float u = is3 ? p4 : x;
        const float v = hi2 ? p4 : x;
        p5 = __shfl_sync(0xFFFFFFFFu, u, srcA, 4);
        p6 = __shfl_sync(0xFFFFFFFFu, v, srcB, 4);
        p4 = x;
    }

    // remainder steps (n % 4), mutually independent (lag >= 4)
    const int rem = n & 3;
    if (rem) {
        const int tt = 4 * ngroups + lq;
        if (lane < rem) {
            const float es = eps[tt] * sigR;
            const float am = fmaf(negR, p5, p4);
            const float q3 = ex2a(am * fmaf(bdg3, p6, bdb3));
            const float q2 = ex2a(am * fmaf(bdg2, p6, bdb2));
            const float q1 = ex2a(am * fmaf(bdg1, p6, bdb1));
            const float y0p = fmaf(g0p, p4, b0p);
            const float y1p = fmaf(g1p, p4, b1p);
            const float y2p = fmaf(g2p, p4, b2p);
            const float y3p = fmaf(g3p, p4, b3p);
            const float S0 = ((q3 + q2) + 1.0f) + q1;
            float s = fmaf(q3, y3p, y0p);
            s = fmaf(q2, y2p, s);
            const float S1p = fmaf(q1, y1p, s);
            out[tt] = fmaf(S1p, rcpa(S0), es);
        }
    }
}

extern "C" void kernel_launch(void* const* d_in, const int* in_sizes, int n_in,
                              void* d_out, int out_size)
{
    const float* params = (const float*)d_in[0];
    const float* eps    = (const float*)d_in[1];
    float* out          = (float*)d_out;
    const int n = in_sizes[1];

    bh_scan_kernel<<<1, 32>>>(params, eps, out, n);
}

// round 11
// speedup vs baseline: 1.1198x; 1.1198x over previous
#include <cuda_runtime.h>
#include <cuda_bf16.h>

// BrockHommes exact sequential scan, lag-4 dependence => 4-way parallel.
// One warp; lanes 0..3 of each quad compute one timestep of the group of 4
// (replicated across 8 quads => warp stays converged, no WARPSYNC). Window
// exchanged with two width-4 shuffles per group.
//
// In-order single-warp issue discipline (validated R3 vs R6): keep the loop
// top BEFORE the first chain op under the SHFL latency shadow (~26 cyc incl.
// back-edge): only es-mul, prefetch rotate, LDG. All other off-chain work
// (y' FMAs) goes AFTER the EX2 issues, inside the MUFU latency shadow.
// 1/R folded into y' so the epilogue is fma(S1', rcp(S0), es).

__device__ __forceinline__ float ex2a(float x) {
    float r; asm("ex2.approx.ftz.f32 %0, %1;" : "=f"(r) : "f"(x)); return r;
}
__device__ __forceinline__ float rcpa(float x) {
    float r; asm("rcp.approx.ftz.f32 %0, %1;" : "=f"(r) : "f"(x)); return r;
}

__global__ void __launch_bounds__(32, 1) bh_scan_kernel(
    const float* __restrict__ params,
    const float* __restrict__ eps,
    float* __restrict__ out,
    int n)
{
    const int lane = (int)threadIdx.x;
    const int lq   = lane & 3;

    // --- derived parameters (uniform) ---
    const float beta  = expf(params[0]);
    const float sigma = expf(params[9]);          // params[-2]
    const float R     = 1.0f + expf(params[10]);  // params[-1]
    const float negR  = -R;
    const float Rinv  = 1.0f / R;
    const float sigR  = sigma * Rinv;
    const float beta2 = beta * 1.44269504088896340736f;  // beta * log2(e)

    const float g0 = params[1], g1 = params[2], g2 = params[3], g3 = params[4];
    const float b0 = params[5], b1 = params[6], b2 = params[7], b3 = params[8];

    // y' coefficients with 1/R folded: y'_i = g'_i*p4 + b'_i ; S1' = S1/R
    const float g0p = g0 * Rinv, g1p = g1 * Rinv, g2p = g2 * Rinv, g3p = g3 * Rinv;
    const float b0p = b0 * Rinv, b1p = b1 * Rinv, b2p = b2 * Rinv, b3p = b3 * Rinv;

    // exponent diffs vs branch 0 (beta*log2e folded)
    const float bdg1 = beta2 * (g1 - g0), bdb1 = beta2 * (b1 - b0);
    const float bdg2 = beta2 * (g2 - g0), bdb2 = beta2 * (b2 - b0);
    const float bdg3 = beta2 * (g3 - g0), bdb3 = beta2 * (b3 - b0);

    const int  srcA = (lq + 3) & 3;   // p5 source within quad
    const int  srcB = (lq + 2) & 3;   // p6 source within quad
    const bool is3  = (lq == 3);
    const bool hi2  = (lq >= 2);
    const bool q0w  = (lane < 4);     // only quad 0 commits stores

    // window for t = 4*grp + lq: p4=x_{t-4}, p5=x_{t-5}, p6=x_{t-6}
    float p4 = 0.0f, p5 = 0.0f, p6 = 0.0f;

    const int ngroups = n >> 2;
    const int nmain   = (ngroups > 2) ? (ngroups - 2) : 0;
    int t = lq;
    float eA = (t     < n) ? eps[t]     : 0.0f;
    float eB = (t + 4 < n) ? eps[t + 4] : 0.0f;

    // main loop: t+8 provably in bounds (t+8 <= 4*(nmain-1)+3+8 < 4*ngroups <= n)
    #pragma unroll 4
    for (int grp = 0; grp < nmain; ++grp, t += 4) {
        // minimal loop top (must fit under SHFL latency shadow)
        const float es = eA * sigR;
        eA = eB;
        eB = eps[t + 8];

        // --- critical chain head ---
        const float am = fmaf(negR, p5, p4);          // xm4 - R*xm5
        const float c1 = fmaf(bdg1, p6, bdb1);
        const float c2 = fmaf(bdg2, p6, bdb2);
        const float c3 = fmaf(bdg3, p6, bdb3);
        const float q1 = ex2a(am * c1);
        const float q2 = ex2a(am * c2);
        const float q3 = ex2a(am * c3);               // issued last -> ready last

        // off-chain work in the MUFU latency shadow
        const float y0p = fmaf(g0p, p4, b0p);
        const float y1p = fmaf(g1p, p4, b1p);
        const float y2p = fmaf(g2p, p4, b2p);
        const float y3p = fmaf(g3p, p4, b3p);

        // last-ready q3 sits at depth 1 in both trees
        const float S0 = ((q1 + q2) + 1.0f) + q3;
        float s = fmaf(q1, y1p, y0p);
        s = fmaf(q2, y2p, s);
        const float S1p = fmaf(q3, y3p, s);

        const float r0 = rcpa(S0);
        const float x  = fmaf(S1p, r0, es);

        // --- window update first (SHFLs issue right after x) ---
        const float u = is3 ? p4 : x;
        const float v = hi2 ? p4 : x;
        p5 = __shfl_sync(0xFFFFFFFFu, u, srcA, 4);
        p6 = __shfl_sync(0xFFFFFFFFu, v, srcB, 4);

        if (q0w) out[t] = x;               // predicated STG, off next chain head
        p4 = x;
    }

    // last (up to 2) full groups: guarded prefetch
    for (int grp = nmain; grp < ngroups; ++grp, t += 4) {
        const float es = eA * sigR;
        eA = eB;
        eB = (t + 8 < n) ? eps[t + 8] : 0.0f;

        const float am = fmaf(negR, p5, p4);
        const float c1 = fmaf(bdg1, p6, bdb1);
        const float c2 = fmaf(bdg2, p6, bdb2);
        const float c3 = fmaf(bdg3, p6, bdb3);
        const float q1 = ex2a(am * c1);
        const float q2 = ex2a(am * c2);
        const float q3 = ex2a(am * c3);
        const float y0p = fmaf(g0p, p4, b0p);
        const float y1p = fmaf(g1p, p4, b1p);
        const float y2p = fmaf(g2p, p4, b2p);
        const float y3p = fmaf(g3p, p4, b3p);
        const float S0 = ((q1 + q2) + 1.0f) + q3;
        float s = fmaf(q1, y1p, y0p);
        s = fmaf(q2, y2p, s);
        const float S1p = fmaf(q3, y3p, s);
        const float x = fmaf(S1p, rcpa(S0), es);

        const float u = is3 ? p4 : x;
        const float v = hi2 ? p4 : x;
        p5 = __shfl_sync(0xFFFFFFFFu, u, srcA, 4);
        p6 = __shfl_sync(0xFFFFFFFFu, v, srcB, 4);

        if (q0w) out[t] = x;
        p4 = x;
    }

    // remainder steps (n % 4), mutually independent (lag >= 4)
    const int rem = n & 3;
    if (rem) {
        const int tt = 4 * ngroups + lq;
        if (lane < rem) {
            const float es = eps[tt] * sigR;
            const float am = fmaf(negR, p5, p4);
            const float q1 = ex2a(am * fmaf(bdg1, p6, bdb1));
            const float q2 = ex2a(am * fmaf(bdg2, p6, bdb2));
            const float q3 = ex2a(am * fmaf(bdg3, p6, bdb3));
            const float y0p = fmaf(g0p, p4, b0p);
            const float y1p = fmaf(g1p, p4, b1p);
            const float y2p = fmaf(g2p, p4, b2p);
            const float y3p = fmaf(g3p, p4, b3p);
            const float S0 = ((q1 + q2) + 1.0f) + q3;
            float s = fmaf(q1, y1p, y0p);
            s = fmaf(q2, y2p, s);
            const float S1p = fmaf(q3, y3p, s);
            out[tt] = fmaf(S1p, rcpa(S0), es);
        }
    }
}

extern "C" void kernel_launch(void* const* d_in, const int* in_sizes, int n_in,
                              void* d_out, int out_size)
{
    const float* params = (const float*)d_in[0];
    const float* eps    = (const float*)d_in[1];
    float* out          = (float*)d_out;
    const int n = in_sizes[1];

    bh_scan_kernel<<<1, 32>>>(params, eps, out, n);
}